// round 1
// baseline (speedup 1.0000x reference)
#include <cuda_runtime.h>

// Problem constants
#define BB   8
#define SEQ  2047
#define LL   2048     // SEQ + 1 (CLS prepended)
#define HH   256
#define NH   8
#define DD   32
#define VV   32001

// ---------------- scratch (static device globals; no allocation) -------------
__device__ int   g_is64;
__device__ float g_pe[LL * HH];                 // 2 MB positional encoding
__device__ float g_qk[NH * HH];                 // per-head query-folded vectors (scaled)
__device__ float g_y0[HH];                      // y at position 0 (same for all b)
__device__ float g_ys[BB * LL * HH];            // 16.8 MB embedded+PE sequence
__device__ float g_sc[BB * NH * LL];            // scores -> probabilities (512 KB)
__device__ float g_ybp[16 * BB * NH * HH];      // partial weighted sums (16 t-chunks)
__device__ float g_yfin[BB * HH];               // final hidden at position 0

// ---------------- dtype detection for x (int64 vs int32) ---------------------
__global__ void k_detect(const unsigned int* __restrict__ x) {
    __shared__ int bad;
    if (threadIdx.x == 0) bad = 0;
    __syncthreads();
    // If x is int64, the hi 32-bit word of each element is 0 (ids <= 32000).
    // If x is int32, odd words are tokens (essentially never all zero).
    for (int i = threadIdx.x; i < 1024; i += 256) {
        if (x[2 * i + 1] != 0u) bad = 1;
    }
    __syncthreads();
    if (threadIdx.x == 0) g_is64 = bad ? 0 : 1;
}

// ---------------- positional encoding table ----------------------------------
__global__ void k_pe() {
    int t = blockIdx.x;          // 0..2047
    int i = threadIdx.x;         // 0..127 (pair index)
    // div = exp(-(2i) * ln(10000)/256)
    float div = expf(-(float)(2 * i) * 0.0359778921f);
    float s, c;
    sincosf((float)t * div, &s, &c);
    g_pe[t * HH + 2 * i]     = s;
    g_pe[t * HH + 2 * i + 1] = c;
}

// ---------------- y0, q0, qk (batch-independent: CLS token id = 2) -----------
__global__ void k_prep(const float* __restrict__ emb,
                       const float* __restrict__ wq,
                       const float* __restrict__ wk) {
    __shared__ float y0s[HH];
    __shared__ float q0s[NH * DD];
    int tid = threadIdx.x;       // 256 threads

    // y0[h] = emb[2,h] + pe[0,h]; pe[0] = [0,1,0,1,...]
    float y0 = emb[2 * HH + tid] + ((tid & 1) ? 1.0f : 0.0f);
    y0s[tid] = y0;
    g_y0[tid] = y0;
    __syncthreads();

    // q0[n,k] = sum_h y0[h] * wq[n,k,h]   (tid = n*32 + k)
    {
        const float* wqr = wq + tid * HH;
        float a = 0.f;
        #pragma unroll 8
        for (int h = 0; h < HH; h++) a += y0s[h] * wqr[h];
        q0s[tid] = a;
    }
    __syncthreads();

    // qk[n,h] = (sum_k q0[n,k] * wk[n,k,h]) / sqrt(32)
    const float scale = 0.17677669529663687f;
    for (int n = 0; n < NH; n++) {
        float s = 0.f;
        #pragma unroll
        for (int k = 0; k < DD; k++)
            s += q0s[n * DD + k] * wk[(n * DD + k) * HH + tid];
        g_qk[n * HH + tid] = s * scale;
    }
}

// ---------------- embed + PE, store ys, compute scores -----------------------
// grid (64 t-tiles of 32, 8 batches), 256 threads
__global__ void k_scores(const void* __restrict__ xraw,
                         const float* __restrict__ emb) {
    __shared__ int toks[32];
    __shared__ float ysm[32 * HH];  // 32 KB
    int tid = threadIdx.x;
    int b  = blockIdx.y;
    int t0 = blockIdx.x * 32;
    int is64 = g_is64;

    if (tid < 32) {
        int t = t0 + tid;
        int id;
        if (t == 0) id = 2;
        else if (is64) id = (int)((const long long*)xraw)[b * SEQ + t - 1];
        else           id = ((const int*)xraw)[b * SEQ + t - 1];
        toks[tid] = id;
    }
    __syncthreads();

    const float4* emb4 = (const float4*)emb;
    const float4* pe4  = (const float4*)g_pe;
    float4* ys4        = (float4*)g_ys;
    #pragma unroll
    for (int idx = tid; idx < 32 * 64; idx += 256) {
        int r = idx >> 6, c = idx & 63;
        float4 e = emb4[(size_t)toks[r] * 64 + c];
        float4 p = pe4[(size_t)(t0 + r) * 64 + c];
        e.x += p.x; e.y += p.y; e.z += p.z; e.w += p.w;
        ((float4*)ysm)[r * 64 + c] = e;
        ys4[((size_t)b * LL + t0 + r) * 64 + c] = e;
    }
    __syncthreads();

    int warp = tid >> 5, lane = tid & 31;

    // preload qk into registers: rq[n][j] = qk[n][lane + 32j]
    float rq[8][8];
    #pragma unroll
    for (int n = 0; n < 8; n++)
        #pragma unroll
        for (int j = 0; j < 8; j++)
            rq[n][j] = g_qk[n * HH + lane + 32 * j];

    for (int r = warp; r < 32; r += 8) {
        float p[8];
        #pragma unroll
        for (int n = 0; n < 8; n++) p[n] = 0.f;
        #pragma unroll
        for (int j = 0; j < 8; j++) {
            float yv = ysm[r * HH + lane + 32 * j];
            #pragma unroll
            for (int n = 0; n < 8; n++) p[n] += yv * rq[n][j];
        }
        #pragma unroll
        for (int n = 0; n < 8; n++) {
            #pragma unroll
            for (int off = 16; off; off >>= 1)
                p[n] += __shfl_xor_sync(0xffffffffu, p[n], off);
        }
        int t = t0 + r;
        #pragma unroll
        for (int n = 0; n < 8; n++)
            if (lane == n) g_sc[((size_t)b * NH + n) * LL + t] = p[n];
    }
}

// ---------------- softmax per (b, n) row --------------------------------------
__global__ void k_softmax() {
    __shared__ float s[LL];      // 8 KB
    __shared__ float red[8];
    int row = blockIdx.x;        // b*8 + n
    int tid = threadIdx.x, lane = tid & 31, warp = tid >> 5;

    float m = -1e30f;
    for (int i = tid; i < LL; i += 256) {
        float v = g_sc[(size_t)row * LL + i];
        s[i] = v;
        m = fmaxf(m, v);
    }
    #pragma unroll
    for (int off = 16; off; off >>= 1) m = fmaxf(m, __shfl_xor_sync(~0u, m, off));
    if (lane == 0) red[warp] = m;
    __syncthreads();
    if (tid == 0) {
        float mm = red[0];
        for (int w = 1; w < 8; w++) mm = fmaxf(mm, red[w]);
        red[0] = mm;
    }
    __syncthreads();
    m = red[0];
    __syncthreads();

    float sum = 0.f;
    for (int i = tid; i < LL; i += 256) {
        float e = expf(s[i] - m);
        s[i] = e;
        sum += e;
    }
    #pragma unroll
    for (int off = 16; off; off >>= 1) sum += __shfl_xor_sync(~0u, sum, off);
    if (lane == 0) red[warp] = sum;
    __syncthreads();
    if (tid == 0) {
        float t = 0.f;
        for (int w = 0; w < 8; w++) t += red[w];
        red[0] = t;
    }
    __syncthreads();
    float inv = 1.f / red[0];
    for (int i = tid; i < LL; i += 256)
        g_sc[(size_t)row * LL + i] = s[i] * inv;
}

// ---------------- weighted sum ybar (partials, deterministic) -----------------
// grid (16 t-chunks of 128, 8 batches), 256 threads
__global__ void k_ybar() {
    __shared__ __align__(16) float P[8][128];
    int tid = threadIdx.x;
    int ch = blockIdx.x;
    int b  = blockIdx.y;
    int c0 = ch * 128;

    for (int i = tid; i < 1024; i += 256) {
        int n = i >> 7, tt = i & 127;
        P[n][tt] = g_sc[((size_t)b * NH + n) * LL + c0 + tt];
    }
    __syncthreads();

    int h = tid;
    float acc[8] = {0.f, 0.f, 0.f, 0.f, 0.f, 0.f, 0.f, 0.f};
    const float* ysb = g_ys + ((size_t)b * LL + c0) * HH + h;
    #pragma unroll 4
    for (int tt = 0; tt < 128; tt += 4) {
        float y0v = ysb[(tt + 0) * HH];
        float y1v = ysb[(tt + 1) * HH];
        float y2v = ysb[(tt + 2) * HH];
        float y3v = ysb[(tt + 3) * HH];
        #pragma unroll
        for (int n = 0; n < 8; n++) {
            float4 p = *(const float4*)&P[n][tt];
            acc[n] += p.x * y0v + p.y * y1v + p.z * y2v + p.w * y3v;
        }
    }
    #pragma unroll
    for (int n = 0; n < 8; n++)
        g_ybp[((size_t)ch * BB + b) * (NH * HH) + n * HH + h] = acc[n];
}

// ---------------- o = ybar @ wv^T, yfin = o @ wo^T + 2*y0 ---------------------
__global__ void k_ov(const float* __restrict__ wv,
                     const float* __restrict__ wo) {
    __shared__ __align__(16) float ybs[NH * HH];  // 8 KB
    __shared__ __align__(16) float os[HH];
    int tid = threadIdx.x;
    int b = blockIdx.x;

    // reduce 16 chunk partials (fixed order -> deterministic)
    for (int i = tid; i < NH * HH; i += 256) {
        float s = 0.f;
        #pragma unroll
        for (int c = 0; c < 16; c++)
            s += g_ybp[((size_t)c * BB + b) * (NH * HH) + i];
        ybs[i] = s;
    }
    __syncthreads();

    // o[n*32+k] = sum_h ybar[n,h] * wv[n,k,h]
    {
        int n = tid >> 5;
        const float4* wvr = (const float4*)(wv + (size_t)tid * HH);
        const float4* ybr = (const float4*)(ybs + n * HH);
        float a = 0.f;
        #pragma unroll 8
        for (int c = 0; c < 64; c++) {
            float4 w = wvr[c]; float4 y = ybr[c];
            a += w.x * y.x + w.y * y.y + w.z * y.z + w.w * y.w;
        }
        os[tid] = a;
    }
    __syncthreads();

    // yfin[h] = sum_j os[j]*wo[h,j] + 2*y0[h]
    {
        const float4* wor = (const float4*)(wo + (size_t)tid * HH);
        const float4* osr = (const float4*)os;
        float a = 0.f;
        #pragma unroll 8
        for (int c = 0; c < 64; c++) {
            float4 w = wor[c]; float4 o = osr[c];
            a += w.x * o.x + w.y * o.y + w.z * o.z + w.w * o.w;
        }
        g_yfin[b * HH + tid] = a + 2.f * g_y0[tid];
    }
}

// ---------------- out[b, v] = yfin[b] . wu[v] ---------------------------------
__global__ void k_out(const float* __restrict__ wu, float* __restrict__ out) {
    __shared__ __align__(16) float yf[BB * HH];   // 8 KB
    int tid = threadIdx.x;
    for (int i = tid; i < BB * HH; i += 256) yf[i] = g_yfin[i];
    __syncthreads();

    int v = blockIdx.x * 256 + tid;
    if (v >= VV) return;

    const float4* wur = (const float4*)(wu + (size_t)v * HH);
    const float4* yf4 = (const float4*)yf;
    float acc[8] = {0.f, 0.f, 0.f, 0.f, 0.f, 0.f, 0.f, 0.f};
    #pragma unroll 4
    for (int c = 0; c < 64; c++) {
        float4 w = wur[c];
        #pragma unroll
        for (int b = 0; b < 8; b++) {
            float4 y = yf4[b * 64 + c];
            acc[b] += w.x * y.x + w.y * y.y + w.z * y.z + w.w * y.w;
        }
    }
    #pragma unroll
    for (int b = 0; b < 8; b++) out[(size_t)b * VV + v] = acc[b];
}

// ---------------- launcher ----------------------------------------------------
extern "C" void kernel_launch(void* const* d_in, const int* in_sizes, int n_in,
                              void* d_out, int out_size) {
    const void*  x   = d_in[0];
    const float* emb = (const float*)d_in[1];
    const float* wq  = (const float*)d_in[2];
    const float* wk  = (const float*)d_in[3];
    const float* wv  = (const float*)d_in[4];
    const float* wo  = (const float*)d_in[5];
    const float* wu  = (const float*)d_in[6];
    float* out = (float*)d_out;

    k_detect<<<1, 256>>>((const unsigned int*)x);
    k_pe<<<LL, 128>>>();
    k_prep<<<1, 256>>>(emb, wq, wk);
    k_scores<<<dim3(64, BB), 256>>>(x, emb);
    k_softmax<<<BB * NH, 256>>>();
    k_ybar<<<dim3(16, BB), 256>>>();
    k_ov<<<BB, 256>>>(wv, wo);
    k_out<<<(VV + 255) / 256, 256>>>(wu, out);
}

// round 2
// speedup vs baseline: 1.2202x; 1.2202x over previous
#include <cuda_runtime.h>

// Problem constants
#define BB   8
#define SEQ  2047
#define LL   2048     // SEQ + 1 (CLS prepended)
#define HH   256
#define NH   8
#define DD   32
#define VV   32001

// ---------------- scratch (static device globals; no allocation) -------------
__device__ int   g_is64;
__device__ float g_pe[LL * HH];                 // 2 MB positional encoding
__device__ float g_qk[NH * HH];                 // per-head folded query vectors (scaled)
__device__ float g_y0[HH];                      // y at position 0 (same for all b)
__device__ float g_se[VV * NH];                 // ~1 MB: qk . emb[v] per head
__device__ float g_pesc[NH * LL];               // qk . pe[t] per head
__device__ float g_sc[BB * NH * LL];            // scores -> probabilities (512 KB)
__device__ float g_ybp[16 * BB * NH * HH];      // partial weighted sums (16 t-chunks)
__device__ float g_yfin[BB * HH];               // final hidden at position 0

// ---------------- dtype detection for x (int64 vs int32) ---------------------
__global__ void k_detect(const unsigned int* __restrict__ x) {
    __shared__ int bad;
    if (threadIdx.x == 0) bad = 0;
    __syncthreads();
    // If x is int64, the hi 32-bit word of each element is 0 (ids <= 32000).
    for (int i = threadIdx.x; i < 1024; i += 256) {
        if (x[2 * i + 1] != 0u) bad = 1;
    }
    __syncthreads();
    if (threadIdx.x == 0) g_is64 = bad ? 0 : 1;
}

// ---------------- y0, q0, qk: one block per head ------------------------------
__global__ void k_prep(const float* __restrict__ emb,
                       const float* __restrict__ wq,
                       const float* __restrict__ wk) {
    int n = blockIdx.x;          // head
    int tid = threadIdx.x;       // 256 threads
    __shared__ float y0s[HH];
    __shared__ float q0s[DD];

    float y0 = emb[2 * HH + tid] + ((tid & 1) ? 1.0f : 0.0f);   // pe[0]=[0,1,0,1..]
    y0s[tid] = y0;
    if (n == 0) g_y0[tid] = y0;
    __syncthreads();

    if (tid < DD) {
        const float* wqr = wq + (size_t)(n * DD + tid) * HH;
        float a = 0.f;
        #pragma unroll 8
        for (int h = 0; h < HH; h++) a += y0s[h] * wqr[h];
        q0s[tid] = a;
    }
    __syncthreads();

    const float scale = 0.17677669529663687f;   // 1/sqrt(32)
    float s = 0.f;
    #pragma unroll
    for (int k = 0; k < DD; k++)
        s += q0s[k] * wk[(size_t)(n * DD + k) * HH + tid];
    g_qk[n * HH + tid] = s * scale;
}

// ---------------- pe table + pesc[n][t] = qk[n] . pe[t] -----------------------
__global__ void k_pe() {
    int t = blockIdx.x;          // 0..2047
    int i = threadIdx.x;         // 0..127 (pair index)
    __shared__ float row[HH];
    float div = expf(-(float)(2 * i) * 0.03597789203f);   // ln(10000)/256
    float s, c;
    sincosf((float)t * div, &s, &c);
    row[2 * i]     = s;
    row[2 * i + 1] = c;
    g_pe[t * HH + 2 * i]     = s;
    g_pe[t * HH + 2 * i + 1] = c;
    __syncthreads();

    int lane = i & 31, warp = i >> 5;     // 4 warps
    for (int n = warp; n < NH; n += 4) {
        float p = 0.f;
        #pragma unroll
        for (int j = lane; j < HH; j += 32) p += g_qk[n * HH + j] * row[j];
        #pragma unroll
        for (int off = 16; off; off >>= 1) p += __shfl_xor_sync(~0u, p, off);
        if (lane == 0) g_pesc[n * LL + t] = p;
    }
}

// ---------------- se[v][n] = qk[n] . emb[v]  (streaming GEMV over vocab) -----
__global__ void k_se(const float* __restrict__ emb) {
    __shared__ float qks[NH * HH];   // 8 KB
    int tid = threadIdx.x;
    for (int i = tid; i < NH * HH; i += 256) qks[i] = g_qk[i];
    __syncthreads();

    int warp = tid >> 5, lane = tid & 31;
    int v = blockIdx.x * 8 + warp;
    if (v >= VV) return;

    const float4* e4 = (const float4*)(emb + (size_t)v * HH);
    float4 a = e4[lane];
    float4 b = e4[lane + 32];

    float p[8];
    #pragma unroll
    for (int n = 0; n < 8; n++) {
        const float4* q4 = (const float4*)(qks + n * HH);
        float4 qa = q4[lane], qb = q4[lane + 32];
        p[n] = a.x * qa.x + a.y * qa.y + a.z * qa.z + a.w * qa.w
             + b.x * qb.x + b.y * qb.y + b.z * qb.z + b.w * qb.w;
    }
    #pragma unroll
    for (int n = 0; n < 8; n++) {
        #pragma unroll
        for (int off = 16; off; off >>= 1)
            p[n] += __shfl_xor_sync(0xffffffffu, p[n], off);
        if (lane == n) g_se[(size_t)v * NH + n] = p[n];
    }
}

// ---------------- fused score-gather + softmax per (b, n) row -----------------
__global__ void k_softmax(const void* __restrict__ xraw) {
    int bn = blockIdx.x;         // b*8 + n
    int b = bn >> 3, n = bn & 7;
    __shared__ float s[LL];      // 8 KB
    __shared__ float red[8];
    int tid = threadIdx.x, lane = tid & 31, warp = tid >> 5;
    int is64 = g_is64;

    float m = -1e30f;
    for (int t = tid; t < LL; t += 256) {
        int tok;
        if (t == 0) tok = 2;
        else if (is64) tok = (int)((const long long*)xraw)[(size_t)b * SEQ + t - 1];
        else           tok = ((const int*)xraw)[(size_t)b * SEQ + t - 1];
        float v = g_se[(size_t)tok * NH + n] + g_pesc[n * LL + t];
        s[t] = v;
        m = fmaxf(m, v);
    }
    #pragma unroll
    for (int off = 16; off; off >>= 1) m = fmaxf(m, __shfl_xor_sync(~0u, m, off));
    if (lane == 0) red[warp] = m;
    __syncthreads();
    if (tid == 0) {
        float mm = red[0];
        for (int w = 1; w < 8; w++) mm = fmaxf(mm, red[w]);
        red[0] = mm;
    }
    __syncthreads();
    m = red[0];
    __syncthreads();

    float sum = 0.f;
    for (int i = tid; i < LL; i += 256) {
        float e = expf(s[i] - m);
        s[i] = e;
        sum += e;
    }
    #pragma unroll
    for (int off = 16; off; off >>= 1) sum += __shfl_xor_sync(~0u, sum, off);
    if (lane == 0) red[warp] = sum;
    __syncthreads();
    if (tid == 0) {
        float t = 0.f;
        for (int w = 0; w < 8; w++) t += red[w];
        red[0] = t;
    }
    __syncthreads();
    float inv = 1.f / red[0];
    for (int i = tid; i < LL; i += 256)
        g_sc[(size_t)bn * LL + i] = s[i] * inv;
}

// ---------------- ybar partials: Sum_t A * (emb[tok] + pe[t]) -----------------
// grid (16 t-chunks of 128, 8 batches), 256 threads (tid = h)
__global__ void k_ybar(const void* __restrict__ xraw,
                       const float* __restrict__ emb) {
    __shared__ float A8[8][128];     // 4 KB
    __shared__ int toks[128];
    int tid = threadIdx.x;
    int ch = blockIdx.x;
    int b  = blockIdx.y;
    int c0 = ch * 128;
    int is64 = g_is64;

    if (tid < 128) {
        int t = c0 + tid;
        int tok;
        if (t == 0) tok = 2;
        else if (is64) tok = (int)((const long long*)xraw)[(size_t)b * SEQ + t - 1];
        else           tok = ((const int*)xraw)[(size_t)b * SEQ + t - 1];
        toks[tid] = tok;
    }
    for (int i = tid; i < 1024; i += 256) {
        int n = i >> 7, tt = i & 127;
        A8[n][tt] = g_sc[((size_t)b * NH + n) * LL + c0 + tt];
    }
    __syncthreads();

    int h = tid;
    float acc[8] = {0.f, 0.f, 0.f, 0.f, 0.f, 0.f, 0.f, 0.f};
    #pragma unroll 4
    for (int tt = 0; tt < 128; tt++) {
        float y = emb[(size_t)toks[tt] * HH + h] + g_pe[(size_t)(c0 + tt) * HH + h];
        #pragma unroll
        for (int n = 0; n < 8; n++) acc[n] += A8[n][tt] * y;
    }
    #pragma unroll
    for (int n = 0; n < 8; n++)
        g_ybp[((size_t)ch * BB + b) * (NH * HH) + n * HH + h] = acc[n];
}

// ---------------- o = ybar @ wv^T, yfin = o @ wo^T + 2*y0 ---------------------
__global__ void k_ov(const float* __restrict__ wv,
                     const float* __restrict__ wo) {
    __shared__ __align__(16) float ybs[NH * HH];  // 8 KB
    __shared__ __align__(16) float os[HH];
    int tid = threadIdx.x;
    int b = blockIdx.x;

    for (int i = tid; i < NH * HH; i += 256) {
        float s = 0.f;
        #pragma unroll
        for (int c = 0; c < 16; c++)
            s += g_ybp[((size_t)c * BB + b) * (NH * HH) + i];
        ybs[i] = s;
    }
    __syncthreads();

    {
        int n = tid >> 5;
        const float4* wvr = (const float4*)(wv + (size_t)tid * HH);
        const float4* ybr = (const float4*)(ybs + n * HH);
        float a = 0.f;
        #pragma unroll 8
        for (int c = 0; c < 64; c++) {
            float4 w = wvr[c]; float4 y = ybr[c];
            a += w.x * y.x + w.y * y.y + w.z * y.z + w.w * y.w;
        }
        os[tid] = a;
    }
    __syncthreads();

    {
        const float4* wor = (const float4*)(wo + (size_t)tid * HH);
        const float4* osr = (const float4*)os;
        float a = 0.f;
        #pragma unroll 8
        for (int c = 0; c < 64; c++) {
            float4 w = wor[c]; float4 o = osr[c];
            a += w.x * o.x + w.y * o.y + w.z * o.z + w.w * o.w;
        }
        g_yfin[b * HH + tid] = a + 2.f * g_y0[tid];
    }
}

// ---------------- out[b, v] = yfin[b] . wu[v] ---------------------------------
__global__ void k_out(const float* __restrict__ wu, float* __restrict__ out) {
    __shared__ __align__(16) float yf[BB * HH];   // 8 KB
    int tid = threadIdx.x;
    for (int i = tid; i < BB * HH; i += 256) yf[i] = g_yfin[i];
    __syncthreads();

    int v = blockIdx.x * 256 + tid;
    if (v >= VV) return;

    const float4* wur = (const float4*)(wu + (size_t)v * HH);
    const float4* yf4 = (const float4*)yf;
    float acc[8] = {0.f, 0.f, 0.f, 0.f, 0.f, 0.f, 0.f, 0.f};
    #pragma unroll 4
    for (int c = 0; c < 64; c++) {
        float4 w = wur[c];
        #pragma unroll
        for (int b = 0; b < 8; b++) {
            float4 y = yf4[b * 64 + c];
            acc[b] += w.x * y.x + w.y * y.y + w.z * y.z + w.w * y.w;
        }
    }
    #pragma unroll
    for (int b = 0; b < 8; b++) out[(size_t)b * VV + v] = acc[b];
}

// ---------------- launcher ----------------------------------------------------
extern "C" void kernel_launch(void* const* d_in, const int* in_sizes, int n_in,
                              void* d_out, int out_size) {
    const void*  x   = d_in[0];
    const float* emb = (const float*)d_in[1];
    const float* wq  = (const float*)d_in[2];
    const float* wk  = (const float*)d_in[3];
    const float* wv  = (const float*)d_in[4];
    const float* wo  = (const float*)d_in[5];
    const float* wu  = (const float*)d_in[6];
    float* out = (float*)d_out;

    k_detect<<<1, 256>>>((const unsigned int*)x);
    k_prep<<<NH, 256>>>(emb, wq, wk);
    k_pe<<<LL, 128>>>();
    k_se<<<(VV + 7) / 8, 256>>>(emb);
    k_softmax<<<BB * NH, 256>>>(x);
    k_ybar<<<dim3(16, BB), 256>>>(x, emb);
    k_ov<<<BB, 256>>>(wv, wo);
    k_out<<<(VV + 255) / 256, 256>>>(wu, out);
}

// round 3
// speedup vs baseline: 1.2994x; 1.0649x over previous
#include <cuda_runtime.h>

// Problem constants
#define BB   8
#define SEQ  2047
#define LL   2048     // SEQ + 1 (CLS prepended)
#define HH   256
#define NH   8
#define DD   32
#define VV   32001
#define NCH  16       // t-chunks for ybar
#define CHT  128      // tokens per chunk

// ---------------- scratch (static device globals; no allocation) -------------
__device__ int   g_is64;
__device__ float g_pe[LL * HH];                 // 2 MB positional encoding
__device__ float g_qk[NH * HH];                 // per-head folded query vectors (scaled)
__device__ float g_y0[HH];                      // y at position 0 (same for all b)
__device__ float g_se[VV * NH];                 // ~1 MB: qk . emb[v], layout [v][n]
__device__ float g_pescT[LL * NH];              // qk . pe[t], layout [t][n]
__device__ float g_zp[BB * NH * NCH];           // partition-function partials
__device__ float g_ybp[NCH * BB * NH * HH];     // weighted-sum partials
__device__ float g_yfin[BB * HH];               // final hidden at position 0

// ---------------- fused: dtype detect (block 8) + per-head prep (blocks 0-7) --
__global__ void k_init(const unsigned int* __restrict__ xw,
                       const float* __restrict__ emb,
                       const float* __restrict__ wq,
                       const float* __restrict__ wk) {
    int blk = blockIdx.x;
    int tid = threadIdx.x;       // 256

    if (blk == NH) {             // ---- dtype detection ----
        __shared__ int bad;
        if (tid == 0) bad = 0;
        __syncthreads();
        for (int i = tid; i < 1024; i += 256)
            if (xw[2 * i + 1] != 0u) bad = 1;
        __syncthreads();
        if (tid == 0) g_is64 = bad ? 0 : 1;
        return;
    }

    // ---- per-head qk prep ----
    int n = blk;
    __shared__ float y0s[HH];
    __shared__ float q0s[DD];

    float y0 = emb[2 * HH + tid] + ((tid & 1) ? 1.0f : 0.0f);   // pe[0]=[0,1,0,1..]
    y0s[tid] = y0;
    if (n == 0) g_y0[tid] = y0;
    __syncthreads();

    if (tid < DD) {
        const float* wqr = wq + (size_t)(n * DD + tid) * HH;
        float a = 0.f;
        #pragma unroll 8
        for (int h = 0; h < HH; h++) a += y0s[h] * wqr[h];
        q0s[tid] = a;
    }
    __syncthreads();

    const float scale = 0.17677669529663687f;   // 1/sqrt(32)
    float s = 0.f;
    #pragma unroll
    for (int k = 0; k < DD; k++)
        s += q0s[k] * wk[(size_t)(n * DD + k) * HH + tid];
    g_qk[n * HH + tid] = s * scale;
}

// ---------------- fused: pe table + pescT (blocks < LL) + se GEMV (rest) ------
__global__ void __launch_bounds__(256) k_mid(const float* __restrict__ emb) {
    int tid = threadIdx.x, lane = tid & 31, warp = tid >> 5;

    if (blockIdx.x < LL) {
        // ---- positional encoding row t + pescT[t][n] ----
        int t = blockIdx.x;
        __shared__ float row[HH];
        if (tid < 128) {
            float div = expf(-(float)(2 * tid) * 0.03597789203f);   // ln(10000)/256
            float s, c;
            sincosf((float)t * div, &s, &c);
            row[2 * tid]     = s;
            row[2 * tid + 1] = c;
            g_pe[(size_t)t * HH + 2 * tid]     = s;
            g_pe[(size_t)t * HH + 2 * tid + 1] = c;
        }
        __syncthreads();
        // warp n computes head-n dot
        int n = warp;
        float p = 0.f;
        #pragma unroll
        for (int j = lane; j < HH; j += 32) p += g_qk[n * HH + j] * row[j];
        #pragma unroll
        for (int off = 16; off; off >>= 1) p += __shfl_xor_sync(~0u, p, off);
        if (lane == 0) g_pescT[t * NH + n] = p;
        return;
    }

    // ---- se[v][n] = qk[n] . emb[v], one row per warp, funnel reduction ----
    __shared__ float qks[NH * HH];
    for (int i = tid; i < NH * HH; i += 256) qks[i] = g_qk[i];
    __syncthreads();

    int v = (blockIdx.x - LL) * 8 + warp;
    if (v >= VV) return;

    const float4* e4 = (const float4*)(emb + (size_t)v * HH);
    float4 a = e4[lane];
    float4 b = e4[lane + 32];

    float p[8];
    #pragma unroll
    for (int n = 0; n < 8; n++) {
        const float4* q4 = (const float4*)(qks + n * HH);
        float4 qa = q4[lane], qb = q4[lane + 32];
        p[n] = a.x * qa.x + a.y * qa.y + a.z * qa.z + a.w * qa.w
             + b.x * qb.x + b.y * qb.y + b.z * qb.z + b.w * qb.w;
    }
    // funnel: 8 values x 32 lanes -> 5 shuffles
    #pragma unroll
    for (int n = 0; n < 4; n++) {
        bool hi = (lane & 8) != 0;
        float keep = hi ? p[n + 4] : p[n];
        float send = hi ? p[n] : p[n + 4];
        p[n] = keep + __shfl_xor_sync(0xffffffffu, send, 8);
    }
    #pragma unroll
    for (int n = 0; n < 2; n++) {
        bool hi = (lane & 4) != 0;
        float keep = hi ? p[n + 2] : p[n];
        float send = hi ? p[n] : p[n + 2];
        p[n] = keep + __shfl_xor_sync(0xffffffffu, send, 4);
    }
    {
        bool hi = (lane & 2) != 0;
        float keep = hi ? p[1] : p[0];
        float send = hi ? p[0] : p[1];
        p[0] = keep + __shfl_xor_sync(0xffffffffu, send, 2);
    }
    p[0] += __shfl_xor_sync(0xffffffffu, p[0], 16);
    p[0] += __shfl_xor_sync(0xffffffffu, p[0], 1);
    // lane with (lane>>1)&7 == h holds head-h total; gather to lanes 0..7
    float r = __shfl_sync(0xffffffffu, p[0], (lane & 7) * 2);
    if (lane < 8) g_se[(size_t)v * NH + lane] = r;
}

// ---------------- fused scores+exp+weighted-sum partials ----------------------
// grid (NCH chunks, BB batches), 256 threads
__global__ void __launch_bounds__(256) k_ybar(const void* __restrict__ xraw,
                                              const float* __restrict__ emb) {
    __shared__ float A8[8][CHT];     // unnormalized probs, 4 KB
    __shared__ int toks[CHT];
    int tid = threadIdx.x, lane = tid & 31, warp = tid >> 5;
    int ch = blockIdx.x;
    int b  = blockIdx.y;
    int c0 = ch * CHT;
    int is64 = g_is64;

    // Phase A: tokens, scores, exp
    if (tid < CHT) {
        int t = c0 + tid;
        int tok;
        if (t == 0) tok = 2;
        else if (is64) tok = (int)((const long long*)xraw)[(size_t)b * SEQ + t - 1];
        else           tok = ((const int*)xraw)[(size_t)b * SEQ + t - 1];
        toks[tid] = tok;

        const float4* se4 = (const float4*)(g_se + (size_t)tok * NH);
        const float4* pp4 = (const float4*)(g_pescT + (size_t)t * NH);
        float4 s0 = se4[0], s1 = se4[1];
        float4 p0 = pp4[0], p1 = pp4[1];
        A8[0][tid] = expf(s0.x + p0.x);
        A8[1][tid] = expf(s0.y + p0.y);
        A8[2][tid] = expf(s0.z + p0.z);
        A8[3][tid] = expf(s0.w + p0.w);
        A8[4][tid] = expf(s1.x + p1.x);
        A8[5][tid] = expf(s1.y + p1.y);
        A8[6][tid] = expf(s1.z + p1.z);
        A8[7][tid] = expf(s1.w + p1.w);
    }
    __syncthreads();

    // Phase B: per-head partition partials (warp n reduces A8[n][:])
    {
        float z = 0.f;
        #pragma unroll
        for (int j = lane; j < CHT; j += 32) z += A8[warp][j];
        #pragma unroll
        for (int off = 16; off; off >>= 1) z += __shfl_xor_sync(~0u, z, off);
        if (lane == 0) g_zp[((size_t)b * NH + warp) * NCH + ch] = z;
    }

    // Phase C: weighted sums over tokens (tid = h)
    int h = tid;
    float acc[8] = {0.f, 0.f, 0.f, 0.f, 0.f, 0.f, 0.f, 0.f};
    #pragma unroll 4
    for (int tt = 0; tt < CHT; tt++) {
        float y = emb[(size_t)toks[tt] * HH + h] + g_pe[(size_t)(c0 + tt) * HH + h];
        #pragma unroll
        for (int n = 0; n < 8; n++) acc[n] += A8[n][tt] * y;
    }
    #pragma unroll
    for (int n = 0; n < 8; n++)
        g_ybp[((size_t)ch * BB + b) * (NH * HH) + n * HH + h] = acc[n];
}

// ---------------- normalize, o = ybar @ wv^T, yfin = o @ wo^T + 2*y0 ----------
__global__ void k_ov(const float* __restrict__ wv,
                     const float* __restrict__ wo) {
    __shared__ __align__(16) float ybs[NH * HH];  // 8 KB
    __shared__ __align__(16) float os[HH];
    __shared__ float zinv[NH];
    int tid = threadIdx.x;
    int b = blockIdx.x;

    if (tid < NH) {
        float z = 0.f;
        #pragma unroll
        for (int c = 0; c < NCH; c++)
            z += g_zp[((size_t)b * NH + tid) * NCH + c];
        zinv[tid] = 1.f / z;
    }
    __syncthreads();

    for (int i = tid; i < NH * HH; i += 256) {
        float s = 0.f;
        #pragma unroll
        for (int c = 0; c < NCH; c++)
            s += g_ybp[((size_t)c * BB + b) * (NH * HH) + i];
        ybs[i] = s * zinv[i >> 8];
    }
    __syncthreads();

    {
        int n = tid >> 5;
        const float4* wvr = (const float4*)(wv + (size_t)tid * HH);
        const float4* ybr = (const float4*)(ybs + n * HH);
        float a = 0.f;
        #pragma unroll 8
        for (int c = 0; c < 64; c++) {
            float4 w = wvr[c]; float4 y = ybr[c];
            a += w.x * y.x + w.y * y.y + w.z * y.z + w.w * y.w;
        }
        os[tid] = a;
    }
    __syncthreads();

    {
        const float4* wor = (const float4*)(wo + (size_t)tid * HH);
        const float4* osr = (const float4*)os;
        float a = 0.f;
        #pragma unroll 8
        for (int c = 0; c < 64; c++) {
            float4 w = wor[c]; float4 o = osr[c];
            a += w.x * o.x + w.y * o.y + w.z * o.z + w.w * o.w;
        }
        g_yfin[b * HH + tid] = a + 2.f * g_y0[tid];
    }
}

// ---------------- out[b, v] = yfin[b] . wu[v] ---------------------------------
__global__ void k_out(const float* __restrict__ wu, float* __restrict__ out) {
    __shared__ __align__(16) float yf[BB * HH];   // 8 KB
    int tid = threadIdx.x;
    for (int i = tid; i < BB * HH; i += 256) yf[i] = g_yfin[i];
    __syncthreads();

    int v = blockIdx.x * 256 + tid;
    if (v >= VV) return;

    const float4* wur = (const float4*)(wu + (size_t)v * HH);
    const float4* yf4 = (const float4*)yf;
    float acc[8] = {0.f, 0.f, 0.f, 0.f, 0.f, 0.f, 0.f, 0.f};
    #pragma unroll 4
    for (int c = 0; c < 64; c++) {
        float4 w = wur[c];
        #pragma unroll
        for (int b = 0; b < 8; b++) {
            float4 y = yf4[b * 64 + c];
            acc[b] += w.x * y.x + w.y * y.y + w.z * y.z + w.w * y.w;
        }
    }
    #pragma unroll
    for (int b = 0; b < 8; b++) out[(size_t)b * VV + v] = acc[b];
}

// ---------------- launcher ----------------------------------------------------
extern "C" void kernel_launch(void* const* d_in, const int* in_sizes, int n_in,
                              void* d_out, int out_size) {
    const void*  x   = d_in[0];
    const float* emb = (const float*)d_in[1];
    const float* wq  = (const float*)d_in[2];
    const float* wk  = (const float*)d_in[3];
    const float* wv  = (const float*)d_in[4];
    const float* wo  = (const float*)d_in[5];
    const float* wu  = (const float*)d_in[6];
    float* out = (float*)d_out;

    k_init<<<NH + 1, 256>>>((const unsigned int*)x, emb, wq, wk);
    k_mid<<<LL + (VV + 7) / 8, 256>>>(emb);
    k_ybar<<<dim3(NCH, BB), 256>>>(x, emb);
    k_ov<<<BB, 256>>>(wv, wo);
    k_out<<<(VV + 255) / 256, 256>>>(wu, out);
}

// round 4
// speedup vs baseline: 1.9110x; 1.4707x over previous
#include <cuda_runtime.h>

// Problem constants
#define BB   8
#define SEQ  2047
#define LL   2048     // SEQ + 1 (CLS prepended)
#define HH   256
#define NH   8
#define DD   32
#define VV   32001
#define NCH  32       // t-chunks for ybar
#define CHT  64       // tokens per chunk

// ---------------- scratch (static device globals; no allocation) -------------
__device__ int   g_is64;
__device__ float g_pe[LL * HH];                 // 2 MB positional encoding
__device__ float g_qk[NH * HH];                 // per-head folded query vectors (scaled)
__device__ float g_y0[HH];                      // y at position 0 (same for all b)
__device__ float g_se[VV * NH];                 // ~1 MB: qk . emb[v], layout [v][n]
__device__ float g_pescT[LL * NH];              // qk . pe[t], layout [t][n]
__device__ float g_zp[BB * NH * NCH];           // partition-function partials
__device__ float g_ybp[NCH * BB * NH * HH];     // weighted-sum partials (2 MB)
__device__ float g_o[BB * HH];                  // attention output per batch
__device__ float g_yfin[BB * HH];               // final hidden at position 0

// ---------------- fused: dtype detect (block 8) + per-head prep (blocks 0-7) --
__global__ void k_init(const unsigned int* __restrict__ xw,
                       const float* __restrict__ emb,
                       const float* __restrict__ wq,
                       const float* __restrict__ wk) {
    int blk = blockIdx.x;
    int tid = threadIdx.x;       // 256

    if (blk == NH) {             // ---- dtype detection ----
        __shared__ int bad;
        if (tid == 0) bad = 0;
        __syncthreads();
        for (int i = tid; i < 1024; i += 256)
            if (xw[2 * i + 1] != 0u) bad = 1;
        __syncthreads();
        if (tid == 0) g_is64 = bad ? 0 : 1;
        return;
    }

    int n = blk;
    __shared__ float y0s[HH];
    __shared__ float q0s[DD];

    float y0 = emb[2 * HH + tid] + ((tid & 1) ? 1.0f : 0.0f);   // pe[0]=[0,1,0,1..]
    y0s[tid] = y0;
    if (n == 0) g_y0[tid] = y0;
    __syncthreads();

    if (tid < DD) {
        const float* wqr = wq + (size_t)(n * DD + tid) * HH;
        float a = 0.f;
        #pragma unroll 8
        for (int h = 0; h < HH; h++) a += y0s[h] * wqr[h];
        q0s[tid] = a;
    }
    __syncthreads();

    const float scale = 0.17677669529663687f;   // 1/sqrt(32)
    float s = 0.f;
    #pragma unroll
    for (int k = 0; k < DD; k++)
        s += q0s[k] * wk[(size_t)(n * DD + k) * HH + tid];
    g_qk[n * HH + tid] = s * scale;
}

// ---------------- fused: pe table + pescT (blocks < LL) + se GEMV (rest) ------
// se: 16 vocab rows per block, 2 per warp (higher MLP).
__global__ void __launch_bounds__(256) k_mid(const float* __restrict__ emb) {
    int tid = threadIdx.x, lane = tid & 31, warp = tid >> 5;

    if (blockIdx.x < LL) {
        int t = blockIdx.x;
        __shared__ float row[HH];
        if (tid < 128) {
            float div = expf(-(float)(2 * tid) * 0.03597789203f);   // ln(10000)/256
            float s, c;
            sincosf((float)t * div, &s, &c);
            row[2 * tid]     = s;
            row[2 * tid + 1] = c;
            g_pe[(size_t)t * HH + 2 * tid]     = s;
            g_pe[(size_t)t * HH + 2 * tid + 1] = c;
        }
        __syncthreads();
        int n = warp;
        float p = 0.f;
        #pragma unroll
        for (int j = lane; j < HH; j += 32) p += g_qk[n * HH + j] * row[j];
        #pragma unroll
        for (int off = 16; off; off >>= 1) p += __shfl_xor_sync(~0u, p, off);
        if (lane == 0) g_pescT[t * NH + n] = p;
        return;
    }

    __shared__ float qks[NH * HH];
    for (int i = tid; i < NH * HH; i += 256) qks[i] = g_qk[i];
    __syncthreads();

    int v0 = (blockIdx.x - LL) * 16 + warp * 2;   // two rows per warp
    int v1 = v0 + 1;
    if (v0 >= VV) return;
    bool has1 = (v1 < VV);

    const float4* e40 = (const float4*)(emb + (size_t)v0 * HH);
    const float4* e41 = (const float4*)(emb + (size_t)(has1 ? v1 : v0) * HH);
    float4 a0 = e40[lane];
    float4 b0 = e40[lane + 32];
    float4 a1 = e41[lane];
    float4 b1 = e41[lane + 32];

    float p0[8], p1[8];
    #pragma unroll
    for (int n = 0; n < 8; n++) {
        const float4* q4 = (const float4*)(qks + n * HH);
        float4 qa = q4[lane], qb = q4[lane + 32];
        p0[n] = a0.x * qa.x + a0.y * qa.y + a0.z * qa.z + a0.w * qa.w
              + b0.x * qb.x + b0.y * qb.y + b0.z * qb.z + b0.w * qb.w;
        p1[n] = a1.x * qa.x + a1.y * qa.y + a1.z * qa.z + a1.w * qa.w
              + b1.x * qb.x + b1.y * qb.y + b1.z * qb.z + b1.w * qb.w;
    }
    // funnel both rows: 8 values x 32 lanes -> 5 shuffles each
    #pragma unroll
    for (int n = 0; n < 4; n++) {
        bool hi = (lane & 8) != 0;
        float k0 = hi ? p0[n + 4] : p0[n], s0 = hi ? p0[n] : p0[n + 4];
        float k1 = hi ? p1[n + 4] : p1[n], s1 = hi ? p1[n] : p1[n + 4];
        p0[n] = k0 + __shfl_xor_sync(~0u, s0, 8);
        p1[n] = k1 + __shfl_xor_sync(~0u, s1, 8);
    }
    #pragma unroll
    for (int n = 0; n < 2; n++) {
        bool hi = (lane & 4) != 0;
        float k0 = hi ? p0[n + 2] : p0[n], s0 = hi ? p0[n] : p0[n + 2];
        float k1 = hi ? p1[n + 2] : p1[n], s1 = hi ? p1[n] : p1[n + 2];
        p0[n] = k0 + __shfl_xor_sync(~0u, s0, 4);
        p1[n] = k1 + __shfl_xor_sync(~0u, s1, 4);
    }
    {
        bool hi = (lane & 2) != 0;
        float k0 = hi ? p0[1] : p0[0], s0 = hi ? p0[0] : p0[1];
        float k1 = hi ? p1[1] : p1[0], s1 = hi ? p1[0] : p1[1];
        p0[0] = k0 + __shfl_xor_sync(~0u, s0, 2);
        p1[0] = k1 + __shfl_xor_sync(~0u, s1, 2);
    }
    p0[0] += __shfl_xor_sync(~0u, p0[0], 16);
    p0[0] += __shfl_xor_sync(~0u, p0[0], 1);
    p1[0] += __shfl_xor_sync(~0u, p1[0], 16);
    p1[0] += __shfl_xor_sync(~0u, p1[0], 1);
    // head-h total lives at lane h*2; gather
    float r0 = __shfl_sync(~0u, p0[0], (lane & 7) * 2);
    float r1 = __shfl_sync(~0u, p1[0], (lane & 7) * 2);
    if (lane < 8) g_se[(size_t)v0 * NH + lane] = r0;
    else if (lane < 16 && has1) g_se[(size_t)v1 * NH + (lane - 8)] = r1;
}

// ---------------- fused scores+exp+weighted-sum partials ----------------------
// grid (NCH chunks, BB batches), 256 threads
__global__ void __launch_bounds__(256) k_ybar(const void* __restrict__ xraw,
                                              const float* __restrict__ emb) {
    __shared__ float A8[8][CHT];
    __shared__ int toks[CHT];
    int tid = threadIdx.x, lane = tid & 31, warp = tid >> 5;
    int ch = blockIdx.x;
    int b  = blockIdx.y;
    int c0 = ch * CHT;
    int is64 = g_is64;

    // Phase A: tokens, scores, exp (unnormalized; scores are O(1), safe)
    if (tid < CHT) {
        int t = c0 + tid;
        int tok;
        if (t == 0) tok = 2;
        else if (is64) tok = (int)((const long long*)xraw)[(size_t)b * SEQ + t - 1];
        else           tok = ((const int*)xraw)[(size_t)b * SEQ + t - 1];
        toks[tid] = tok;

        const float4* se4 = (const float4*)(g_se + (size_t)tok * NH);
        const float4* pp4 = (const float4*)(g_pescT + (size_t)t * NH);
        float4 s0 = se4[0], s1 = se4[1];
        float4 p0 = pp4[0], p1 = pp4[1];
        A8[0][tid] = expf(s0.x + p0.x);
        A8[1][tid] = expf(s0.y + p0.y);
        A8[2][tid] = expf(s0.z + p0.z);
        A8[3][tid] = expf(s0.w + p0.w);
        A8[4][tid] = expf(s1.x + p1.x);
        A8[5][tid] = expf(s1.y + p1.y);
        A8[6][tid] = expf(s1.z + p1.z);
        A8[7][tid] = expf(s1.w + p1.w);
    }
    __syncthreads();

    // Phase B: per-head partition partials (warp n reduces A8[n][:])
    {
        float z = A8[warp][lane] + A8[warp][lane + 32];
        #pragma unroll
        for (int off = 16; off; off >>= 1) z += __shfl_xor_sync(~0u, z, off);
        if (lane == 0) g_zp[((size_t)b * NH + warp) * NCH + ch] = z;
    }

    // Phase C: weighted sums over tokens (tid = h)
    int h = tid;
    float acc[8] = {0.f, 0.f, 0.f, 0.f, 0.f, 0.f, 0.f, 0.f};
    #pragma unroll 4
    for (int tt = 0; tt < CHT; tt++) {
        float y = emb[(size_t)toks[tt] * HH + h] + g_pe[(size_t)(c0 + tt) * HH + h];
        #pragma unroll
        for (int n = 0; n < 8; n++) acc[n] += A8[n][tt] * y;
    }
    #pragma unroll
    for (int n = 0; n < 8; n++)
        g_ybp[((size_t)ch * BB + b) * (NH * HH) + n * HH + h] = acc[n];
}

// ---------------- k_ova: per-(b,n) reduce+normalize, o-slice = ybar @ wv^T ----
// grid 64 = b*NH + n, 256 threads
__global__ void __launch_bounds__(256) k_ova(const float* __restrict__ wv) {
    __shared__ __align__(16) float ybs[HH];
    __shared__ float zinv_s;
    int tid = threadIdx.x, lane = tid & 31, warp = tid >> 5;
    int bn = blockIdx.x;
    int b = bn >> 3, n = bn & 7;

    // partition function (NCH == 32 == warp size)
    if (warp == 0) {
        float z = g_zp[(size_t)bn * NCH + lane];
        #pragma unroll
        for (int off = 16; off; off >>= 1) z += __shfl_xor_sync(~0u, z, off);
        if (lane == 0) zinv_s = 1.f / z;
    }

    // reduce ybp over chunks (tid = h)
    float s = 0.f;
    #pragma unroll
    for (int c = 0; c < NCH; c++)
        s += g_ybp[((size_t)c * BB + b) * (NH * HH) + n * HH + tid];
    __syncthreads();
    ybs[tid] = s * zinv_s;
    __syncthreads();

    // o[b, n*32+k] = ybar . wv[n,k,:]   (8 threads per k, 8 float4 each)
    int k = tid >> 3, g = tid & 7;
    const float4* wvr = (const float4*)(wv + (size_t)(n * DD + k) * HH);
    const float4* yb4 = (const float4*)ybs;
    float a = 0.f;
    #pragma unroll
    for (int c = 0; c < 8; c++) {
        float4 w = wvr[g * 8 + c]; float4 y = yb4[g * 8 + c];
        a += w.x * y.x + w.y * y.y + w.z * y.z + w.w * y.w;
    }
    a += __shfl_xor_sync(~0u, a, 4);
    a += __shfl_xor_sync(~0u, a, 2);
    a += __shfl_xor_sync(~0u, a, 1);
    if (g == 0) g_o[b * HH + n * DD + k] = a;
}

// ---------------- k_ovb: yfin = o @ wo^T + 2*y0 -------------------------------
// grid 64 = b*8 + hc, 256 threads; each block does 32 h-outputs
__global__ void __launch_bounds__(256) k_ovb(const float* __restrict__ wo) {
    __shared__ __align__(16) float os[HH];
    int tid = threadIdx.x;
    int blk = blockIdx.x;
    int b = blk >> 3, hc = blk & 7;

    if (tid < HH) os[tid] = g_o[b * HH + tid];
    __syncthreads();

    int i = tid >> 3, g = tid & 7;       // h = hc*32 + i
    int h = hc * 32 + i;
    const float4* wor = (const float4*)(wo + (size_t)h * HH);
    const float4* o4 = (const float4*)os;
    float a = 0.f;
    #pragma unroll
    for (int c = 0; c < 8; c++) {
        float4 w = wor[g * 8 + c]; float4 o = o4[g * 8 + c];
        a += w.x * o.x + w.y * o.y + w.z * o.z + w.w * o.w;
    }
    a += __shfl_xor_sync(~0u, a, 4);
    a += __shfl_xor_sync(~0u, a, 2);
    a += __shfl_xor_sync(~0u, a, 1);
    if (g == 0) g_yfin[b * HH + h] = a + 2.f * g_y0[h];
}

// ---------------- out[b, v] = yfin[b] . wu[v] ---------------------------------
__global__ void k_out(const float* __restrict__ wu, float* __restrict__ out) {
    __shared__ __align__(16) float yf[BB * HH];   // 8 KB
    int tid = threadIdx.x;
    for (int i = tid; i < BB * HH; i += 256) yf[i] = g_yfin[i];
    __syncthreads();

    int v = blockIdx.x * 256 + tid;
    if (v >= VV) return;

    const float4* wur = (const float4*)(wu + (size_t)v * HH);
    const float4* yf4 = (const float4*)yf;
    float acc[8] = {0.f, 0.f, 0.f, 0.f, 0.f, 0.f, 0.f, 0.f};
    #pragma unroll 4
    for (int c = 0; c < 64; c++) {
        float4 w = wur[c];
        #pragma unroll
        for (int b = 0; b < 8; b++) {
            float4 y = yf4[b * 64 + c];
            acc[b] += w.x * y.x + w.y * y.y + w.z * y.z + w.w * y.w;
        }
    }
    #pragma unroll
    for (int b = 0; b < 8; b++) out[(size_t)b * VV + v] = acc[b];
}

// ---------------- launcher ----------------------------------------------------
extern "C" void kernel_launch(void* const* d_in, const int* in_sizes, int n_in,
                              void* d_out, int out_size) {
    const void*  x   = d_in[0];
    const float* emb = (const float*)d_in[1];
    const float* wq  = (const float*)d_in[2];
    const float* wk  = (const float*)d_in[3];
    const float* wv  = (const float*)d_in[4];
    const float* wo  = (const float*)d_in[5];
    const float* wu  = (const float*)d_in[6];
    float* out = (float*)d_out;

    k_init<<<NH + 1, 256>>>((const unsigned int*)x, emb, wq, wk);
    k_mid<<<LL + (VV + 15) / 16, 256>>>(emb);
    k_ybar<<<dim3(NCH, BB), 256>>>(x, emb);
    k_ova<<<BB * NH, 256>>>(wv);
    k_ovb<<<BB * NH, 256>>>(wo);
    k_out<<<(VV + 255) / 256, 256>>>(wu, out);
}